// round 14
// baseline (speedup 1.0000x reference)
#include <cuda_runtime.h>
#include <cuda_fp16.h>
#include <cstdint>

#define Bq 4
#define Nq 2048
#define FIN 128
#define Hq 4
#define HIDq 32
#define NIC 32
#define KC 64
#define NCHUNK (Nq/KC)     // 32
#define JS 4               // K-splits for k4 (fp32 partial sums + grid parallelism)
#define CPS (NCHUNK/JS)    // 8 chunks per split
#define HT_SCALE 32768.0f          // 2^15, exact
#define HT_INV   (1.0f/32768.0f)

#define RSH 72                       // halves per padded row (conflict-free frags)
#define A_ROWS 64
#define A_STAGE_H (A_ROWS*RSH)       // 4608 halves
#define B_STAGE_H (32*RSH)           // 2304 halves
#define STAGE_H   (A_STAGE_H + B_STAGE_H)   // 6912 halves = 13824 B

// Scratch (device globals: no allocations allowed)
__device__ float  g_ht[Bq*Hq*Nq*HIDq];           // [bh][n][d]
__device__ float  g_si[Bq*Hq*Nq];                // [bh][n]
__device__ float  g_lp[NIC*Bq*Hq*Nq];            // partial column sums
__device__ __align__(256) __half g_w[(size_t)Bq*Hq*Nq*Nq];   // fp16 weights [bh][i][j]
__device__ __align__(256) __half g_htT[Bq*Hq*HIDq*Nq];       // fp16 (htp^T * 2^15) [bh][d][j]
__device__ float  g_po[(size_t)JS*Bq*Nq*Hq*HIDq];// k4 partial outputs [jz][b][i][h*32+d]

// ---------------- k1: ht = h @ W (per-row), s_i = <ht, a_i>  [R10 exact] ----------------
__global__ void k1_proj(const float* __restrict__ hin,
                        const float* __restrict__ W,
                        const float* __restrict__ a) {
    int bn = blockIdx.x;
    int b = bn >> 11, n = bn & (Nq - 1);
    __shared__ float sh[FIN];
    int t = threadIdx.x;
    sh[t] = hin[bn * FIN + t];
    __syncthreads();
    float acc = 0.f;
#pragma unroll 16
    for (int k = 0; k < FIN; k++) acc += sh[k] * W[(k << 7) + t];
    int hh = t >> 5, d = t & 31;
    g_ht[(((b * Hq + hh) * Nq) + n) * HIDq + d] = acc;
    float v = acc * a[hh * 68 + d];
#pragma unroll
    for (int o = 16; o > 0; o >>= 1) v += __shfl_xor_sync(0xffffffffu, v, o);
    if (d == 0) g_si[(b * Hq + hh) * Nq + n] = v;
}

// ------- k2: w = fp16(mask * exp(s_i + s_e)), partial column sums  [R10 exact] -------
__global__ __launch_bounds__(256)
void k2_w(const int* __restrict__ adj,
          const float4* __restrict__ edge,
          const float* __restrict__ a) {
    int t  = threadIdx.x;
    int j  = blockIdx.y * 256 + t;
    int b  = blockIdx.z;
    int ic = blockIdx.x;
    int i0 = ic * 64;

    __shared__ float ssi[Hq][64];
    {
        int hh = t >> 6, il = t & 63;
        ssi[hh][il] = g_si[(b * Hq + hh) * Nq + i0 + il];
    }
    float ae[4][4];
#pragma unroll
    for (int hh = 0; hh < 4; hh++)
#pragma unroll
        for (int e = 0; e < 4; e++) ae[hh][e] = a[hh * 68 + 2 * HIDq + e];
    __syncthreads();

    float acc0 = 0.f, acc1 = 0.f, acc2 = 0.f, acc3 = 0.f;
    const int*    adjp = adj  + (size_t)(b * Nq + i0) * Nq + j;
    const float4* ep   = edge + (size_t)(b * Nq + i0) * Nq + j;
    __half* wp = g_w + (size_t)(b * Hq * Nq + i0) * Nq + j;
    const size_t hstride = (size_t)Nq * Nq;

#pragma unroll 4
    for (int ii = 0; ii < 64; ii++) {
        int ad = adjp[(size_t)ii * Nq];
        float4 e4 = ep[(size_t)ii * Nq];
        float v0 = ssi[0][ii] + e4.x*ae[0][0] + e4.y*ae[0][1] + e4.z*ae[0][2] + e4.w*ae[0][3];
        float v1 = ssi[1][ii] + e4.x*ae[1][0] + e4.y*ae[1][1] + e4.z*ae[1][2] + e4.w*ae[1][3];
        float v2 = ssi[2][ii] + e4.x*ae[2][0] + e4.y*ae[2][1] + e4.z*ae[2][2] + e4.w*ae[2][3];
        float v3 = ssi[3][ii] + e4.x*ae[3][0] + e4.y*ae[3][1] + e4.z*ae[3][2] + e4.w*ae[3][3];
        __half w0 = (ad > 0) ? __float2half_rn(fminf(__expf(v0), 60000.f)) : __half(0.f);
        __half w1 = (ad > 0) ? __float2half_rn(fminf(__expf(v1), 60000.f)) : __half(0.f);
        __half w2 = (ad > 0) ? __float2half_rn(fminf(__expf(v2), 60000.f)) : __half(0.f);
        __half w3 = (ad > 0) ? __float2half_rn(fminf(__expf(v3), 60000.f)) : __half(0.f);
        size_t ro = (size_t)ii * Nq;
        wp[ro]             = w0;
        wp[ro + hstride]   = w1;
        wp[ro + 2*hstride] = w2;
        wp[ro + 3*hstride] = w3;
        acc0 += __half2float(w0); acc1 += __half2float(w1);
        acc2 += __half2float(w2); acc3 += __half2float(w3);
    }
    int base = ((ic * Bq + b) * Hq) * Nq + j;
    g_lp[base + 0 * Nq] = acc0;
    g_lp[base + 1 * Nq] = acc1;
    g_lp[base + 2 * Nq] = acc2;
    g_lp[base + 3 * Nq] = acc3;
}

// ------- k3: l reduction, htT[bh][d][j] = fp16(ht[j][d]/l[j] * 2^15)  [R10 exact] -------
__global__ __launch_bounds__(256)
void k3_scale_T() {
    int bh = blockIdx.y;
    int j0 = blockIdx.x * 256;
    int t = threadIdx.x;
    __shared__ float sm[256][33];
    __shared__ float sinv[256];
    int b = bh >> 2, h = bh & 3;
    float l = 0.f;
#pragma unroll
    for (int ic = 0; ic < NIC; ic++) l += g_lp[((ic * Bq + b) * Hq + h) * Nq + j0 + t];
    sinv[t] = (l > 0.f) ? HT_SCALE / l : 0.f;

    const float4* hp = (const float4*)(g_ht + ((size_t)bh * Nq + j0) * HIDq);
    for (int q = t; q < 256 * HIDq / 4; q += 256) {
        float4 v = hp[q];
        int r = q >> 3, d0 = (q & 7) * 4;
        sm[r][d0] = v.x; sm[r][d0+1] = v.y; sm[r][d0+2] = v.z; sm[r][d0+3] = v.w;
    }
    __syncthreads();
    for (int q = t; q < HIDq * 256; q += 256) {
        int d = q >> 8, r = q & 255;
        g_htT[((size_t)bh * HIDq + d) * Nq + j0 + r] = __float2half_rn(sm[r][d] * sinv[r]);
    }
}

// ---------------- k4: mma.sync fp16 GEMM, K-split partials ----------------
// Synchronous double-buffered LDG.128 -> STS.128 staging. NO cp.async anywhere.
// MMA block / smem layout / fragment reads byte-identical to R10's.
__global__ __launch_bounds__(128)
void k4_mma() {
    __shared__ __align__(16) __half sm2[2][STAGE_H];   // 2 x 13824 B static

    int t = threadIdx.x;
    int w = t >> 5, lane = t & 31;
    int bh = blockIdx.y;
    int i0 = blockIdx.x * 64;
    int jz = blockIdx.z;
    int b = bh >> 2, h = bh & 3;

    // staging geometry (same element mapping as R10)
    int arow = t >> 1, aseg0 = (t & 1) * 4;     // 64 rows, 2 thr/row, 4 x 16B segs
    int brow = t >> 2, bseg0 = (t & 3) * 2;     // 32 rows, 4 thr/row, 2 x 16B segs
    const uint4* aSrc = (const uint4*)(g_w   + ((size_t)bh * Nq + i0 + arow) * Nq);
    const uint4* bSrc = (const uint4*)(g_htT + ((size_t)bh * HIDq + brow) * Nq);

    // fragment geometry
    int gro = lane >> 2;      // group row / n-col
    int tig = lane & 3;       // thread-in-group

    float acc[4][4];
#pragma unroll
    for (int nt = 0; nt < 4; nt++)
#pragma unroll
        for (int q = 0; q < 4; q++) acc[nt][q] = 0.f;

    uint4 ra0, ra1, ra2, ra3, rb0, rb1;
    const int c0 = jz * CPS;

#define LDGC(c) do {                                      \
        const uint4* ap_ = aSrc + (c) * 8 + aseg0;        \
        ra0 = ap_[0]; ra1 = ap_[1]; ra2 = ap_[2]; ra3 = ap_[3]; \
        const uint4* bp_ = bSrc + (c) * 8 + bseg0;        \
        rb0 = bp_[0]; rb1 = bp_[1];                       \
    } while (0)

    LDGC(c0);
    for (int cc = 0; cc < CPS; cc++) {
        int buf = cc & 1;
        {
            __half* dA = &sm2[buf][arow * RSH];
            *(uint4*)(dA + (aseg0 + 0) * 8) = ra0;
            *(uint4*)(dA + (aseg0 + 1) * 8) = ra1;
            *(uint4*)(dA + (aseg0 + 2) * 8) = ra2;
            *(uint4*)(dA + (aseg0 + 3) * 8) = ra3;
            __half* dB = &sm2[buf][A_STAGE_H + brow * RSH];
            *(uint4*)(dB + (bseg0 + 0) * 8) = rb0;
            *(uint4*)(dB + (bseg0 + 1) * 8) = rb1;
        }
        __syncthreads();
        if (cc + 1 < CPS) LDGC(c0 + cc + 1);   // overlap next-chunk LDG with MMA

        const __half* sA = sm2[buf];
        const __half* sB = sm2[buf] + A_STAGE_H;

#pragma unroll
        for (int ks = 0; ks < 4; ks++) {
            int kb = ks * 16;
            const __half* ap = sA + (w * 16 + gro) * RSH + kb + 2 * tig;
            uint32_t a0 = *(const uint32_t*)(ap);
            uint32_t a1 = *(const uint32_t*)(ap + 8 * RSH);
            uint32_t a2 = *(const uint32_t*)(ap + 8);
            uint32_t a3 = *(const uint32_t*)(ap + 8 * RSH + 8);
#pragma unroll
            for (int nt = 0; nt < 4; nt++) {
                const __half* bp = sB + (nt * 8 + gro) * RSH + kb + 2 * tig;
                uint32_t b0 = *(const uint32_t*)(bp);
                uint32_t b1 = *(const uint32_t*)(bp + 8);
                asm volatile(
                    "mma.sync.aligned.m16n8k16.row.col.f32.f16.f16.f32 "
                    "{%0,%1,%2,%3}, {%4,%5,%6,%7}, {%8,%9}, {%0,%1,%2,%3};"
                    : "+f"(acc[nt][0]), "+f"(acc[nt][1]),
                      "+f"(acc[nt][2]), "+f"(acc[nt][3])
                    : "r"(a0), "r"(a1), "r"(a2), "r"(a3), "r"(b0), "r"(b1));
            }
        }
    }

    // epilogue: partial out [jz][b][i][h*32 + d]; undo 2^15
    float* po = g_po + (size_t)jz * (Bq * Nq * Hq * HIDq);
    int r0 = i0 + w * 16 + gro;
#pragma unroll
    for (int nt = 0; nt < 4; nt++) {
        int col = h * HIDq + nt * 8 + 2 * tig;
        float2 v0 = {acc[nt][0] * HT_INV, acc[nt][1] * HT_INV};
        float2 v1 = {acc[nt][2] * HT_INV, acc[nt][3] * HT_INV};
        *(float2*)(po + ((size_t)(b * Nq + r0))     * (Hq * HIDq) + col) = v0;
        *(float2*)(po + ((size_t)(b * Nq + r0 + 8)) * (Hq * HIDq) + col) = v1;
    }
}

// ---------------- k5: reduce partials -> out ----------------
__global__ void k5_reduce(float4* __restrict__ out) {
    int idx = blockIdx.x * 256 + threadIdx.x;   // float4 index
    const float4* po = (const float4*)g_po;
    const int stride = Bq * Nq * Hq * HIDq / 4;
    float4 s = po[idx];
#pragma unroll
    for (int jz = 1; jz < JS; jz++) {
        float4 v = po[(size_t)jz * stride + idx];
        s.x += v.x; s.y += v.y; s.z += v.z; s.w += v.w;
    }
    out[idx] = s;
}

extern "C" void kernel_launch(void* const* d_in, const int* in_sizes, int n_in,
                              void* d_out, int out_size) {
    const float* hin  = (const float*)d_in[0];
    const int*   adj  = (const int*)  d_in[1];
    const float* edge = (const float*)d_in[2];
    const float* W    = (const float*)d_in[3];
    const float* a    = (const float*)d_in[4];
    float* out = (float*)d_out;

    k1_proj<<<Bq * Nq, 128>>>(hin, W, a);
    k2_w<<<dim3(NIC, Nq / 256, Bq), 256>>>(adj, (const float4*)edge, a);
    k3_scale_T<<<dim3(Nq / 256, Bq * Hq), 256>>>();
    k4_mma<<<dim3(Nq / 64, Bq * Hq, JS), 128>>>();
    k5_reduce<<<(Bq * Nq * Hq * HIDq / 4) / 256, 256>>>((float4*)out);
}

// round 15
// speedup vs baseline: 1.0224x; 1.0224x over previous
#include <cuda_runtime.h>
#include <cuda_fp16.h>
#include <cstdint>

#define Bq 4
#define Nq 2048
#define FIN 128
#define Hq 4
#define HIDq 32
#define NIC 32
#define KC 64
#define NCHUNK (Nq/KC)     // 32
#define JS 2               // K-splits for k4
#define CPS (NCHUNK/JS)    // 16 chunks per split
#define HT_SCALE 32768.0f          // 2^15, exact
#define HT_INV   (1.0f/32768.0f)

#define RSH 72                       // halves per padded row (conflict-free frags)
#define A_ROWS 64
#define A_STAGE_H (A_ROWS*RSH)       // 4608 halves
#define B_STAGE_H (32*RSH)           // 2304 halves
#define STAGE_H   (A_STAGE_H + B_STAGE_H)   // 6912 halves = 13824 B

// Scratch (device globals: no allocations allowed)
__device__ float  g_ht[Bq*Hq*Nq*HIDq];           // [bh][n][d]
__device__ float  g_si[Bq*Hq*Nq];                // [bh][n]
__device__ float  g_lp[NIC*Bq*Hq*Nq];            // partial column sums
__device__ __align__(256) __half g_w[(size_t)Bq*Hq*Nq*Nq];   // fp16 weights [bh][i][j]
__device__ __align__(256) __half g_htT[Bq*Hq*HIDq*Nq];       // fp16 (htp^T * 2^15) [bh][d][j]
__device__ float  g_po[(size_t)JS*Bq*Nq*Hq*HIDq];// k4 partial outputs [jz][b][i][h*32+d]

__device__ __forceinline__ uint32_t s2u(const void* p) {
    uint32_t a;
    asm("{ .reg .u64 t; cvta.to.shared.u64 t, %1; cvt.u32.u64 %0, t; }" : "=r"(a) : "l"(p));
    return a;
}

// ---------------- k1: ht = h @ W (per-row), s_i = <ht, a_i>  [R14 exact] ----------------
__global__ void k1_proj(const float* __restrict__ hin,
                        const float* __restrict__ W,
                        const float* __restrict__ a) {
    int bn = blockIdx.x;
    int b = bn >> 11, n = bn & (Nq - 1);
    __shared__ float sh[FIN];
    int t = threadIdx.x;
    sh[t] = hin[bn * FIN + t];
    __syncthreads();
    float acc = 0.f;
#pragma unroll 16
    for (int k = 0; k < FIN; k++) acc += sh[k] * W[(k << 7) + t];
    int hh = t >> 5, d = t & 31;
    g_ht[(((b * Hq + hh) * Nq) + n) * HIDq + d] = acc;
    float v = acc * a[hh * 68 + d];
#pragma unroll
    for (int o = 16; o > 0; o >>= 1) v += __shfl_xor_sync(0xffffffffu, v, o);
    if (d == 0) g_si[(b * Hq + hh) * Nq + n] = v;
}

// ------- k2: w = fp16(mask * exp(s_i + s_e)), partial column sums  [R14 exact] -------
__global__ __launch_bounds__(256)
void k2_w(const int* __restrict__ adj,
          const float4* __restrict__ edge,
          const float* __restrict__ a) {
    int t  = threadIdx.x;
    int j  = blockIdx.y * 256 + t;
    int b  = blockIdx.z;
    int ic = blockIdx.x;
    int i0 = ic * 64;

    __shared__ float ssi[Hq][64];
    {
        int hh = t >> 6, il = t & 63;
        ssi[hh][il] = g_si[(b * Hq + hh) * Nq + i0 + il];
    }
    float ae[4][4];
#pragma unroll
    for (int hh = 0; hh < 4; hh++)
#pragma unroll
        for (int e = 0; e < 4; e++) ae[hh][e] = a[hh * 68 + 2 * HIDq + e];
    __syncthreads();

    float acc0 = 0.f, acc1 = 0.f, acc2 = 0.f, acc3 = 0.f;
    const int*    adjp = adj  + (size_t)(b * Nq + i0) * Nq + j;
    const float4* ep   = edge + (size_t)(b * Nq + i0) * Nq + j;
    __half* wp = g_w + (size_t)(b * Hq * Nq + i0) * Nq + j;
    const size_t hstride = (size_t)Nq * Nq;

#pragma unroll 4
    for (int ii = 0; ii < 64; ii++) {
        int ad = adjp[(size_t)ii * Nq];
        float4 e4 = ep[(size_t)ii * Nq];
        float v0 = ssi[0][ii] + e4.x*ae[0][0] + e4.y*ae[0][1] + e4.z*ae[0][2] + e4.w*ae[0][3];
        float v1 = ssi[1][ii] + e4.x*ae[1][0] + e4.y*ae[1][1] + e4.z*ae[1][2] + e4.w*ae[1][3];
        float v2 = ssi[2][ii] + e4.x*ae[2][0] + e4.y*ae[2][1] + e4.z*ae[2][2] + e4.w*ae[2][3];
        float v3 = ssi[3][ii] + e4.x*ae[3][0] + e4.y*ae[3][1] + e4.z*ae[3][2] + e4.w*ae[3][3];
        __half w0 = (ad > 0) ? __float2half_rn(fminf(__expf(v0), 60000.f)) : __half(0.f);
        __half w1 = (ad > 0) ? __float2half_rn(fminf(__expf(v1), 60000.f)) : __half(0.f);
        __half w2 = (ad > 0) ? __float2half_rn(fminf(__expf(v2), 60000.f)) : __half(0.f);
        __half w3 = (ad > 0) ? __float2half_rn(fminf(__expf(v3), 60000.f)) : __half(0.f);
        size_t ro = (size_t)ii * Nq;
        wp[ro]             = w0;
        wp[ro + hstride]   = w1;
        wp[ro + 2*hstride] = w2;
        wp[ro + 3*hstride] = w3;
        acc0 += __half2float(w0); acc1 += __half2float(w1);
        acc2 += __half2float(w2); acc3 += __half2float(w3);
    }
    int base = ((ic * Bq + b) * Hq) * Nq + j;
    g_lp[base + 0 * Nq] = acc0;
    g_lp[base + 1 * Nq] = acc1;
    g_lp[base + 2 * Nq] = acc2;
    g_lp[base + 3 * Nq] = acc3;
}

// ------- k3: l reduction, htT[bh][d][j] = fp16(ht[j][d]/l[j] * 2^15)  [R14 exact] -------
__global__ __launch_bounds__(256)
void k3_scale_T() {
    int bh = blockIdx.y;
    int j0 = blockIdx.x * 256;
    int t = threadIdx.x;
    __shared__ float sm[256][33];
    __shared__ float sinv[256];
    int b = bh >> 2, h = bh & 3;
    float l = 0.f;
#pragma unroll
    for (int ic = 0; ic < NIC; ic++) l += g_lp[((ic * Bq + b) * Hq + h) * Nq + j0 + t];
    sinv[t] = (l > 0.f) ? HT_SCALE / l : 0.f;

    const float4* hp = (const float4*)(g_ht + ((size_t)bh * Nq + j0) * HIDq);
    for (int q = t; q < 256 * HIDq / 4; q += 256) {
        float4 v = hp[q];
        int r = q >> 3, d0 = (q & 7) * 4;
        sm[r][d0] = v.x; sm[r][d0+1] = v.y; sm[r][d0+2] = v.z; sm[r][d0+3] = v.w;
    }
    __syncthreads();
    for (int q = t; q < HIDq * 256; q += 256) {
        int d = q >> 8, r = q & 255;
        g_htT[((size_t)bh * HIDq + d) * Nq + j0 + r] = __float2half_rn(sm[r][d] * sinv[r]);
    }
}

// ---------------- k4: mma.sync fp16 GEMM, K-split partials ----------------
// Synchronous double-buffered LDG.128 -> STS.128 (deterministic, no cp.async).
// Fragment loads via ldmatrix.x4 (values byte-identical to R14 scalar LDS).
__global__ __launch_bounds__(128)
void k4_mma() {
    __shared__ __align__(16) __half sm2[2][STAGE_H];   // 2 x 13824 B static

    int t = threadIdx.x;
    int w = t >> 5, lane = t & 31;
    int bh = blockIdx.y;
    int i0 = blockIdx.x * 64;
    int jz = blockIdx.z;
    int b = bh >> 2, h = bh & 3;

    // staging geometry (R14 exact element mapping)
    int arow = t >> 1, aseg0 = (t & 1) * 4;     // 64 rows, 2 thr/row, 4 x 16B segs
    int brow = t >> 2, bseg0 = (t & 3) * 2;     // 32 rows, 4 thr/row, 2 x 16B segs
    const uint4* aSrc = (const uint4*)(g_w   + ((size_t)bh * Nq + i0 + arow) * Nq);
    const uint4* bSrc = (const uint4*)(g_htT + ((size_t)bh * HIDq + brow) * Nq);

    // fragment geometry
    int gro = lane >> 2;      // group row / n-col
    int tig = lane & 3;       // thread-in-group

    // ldmatrix lane geometry (byte offsets within a stage buffer)
    int mat = lane >> 3, lr = lane & 7;
    uint32_t smb0 = s2u(sm2[0]);
    uint32_t smb1 = s2u(sm2[1]);
    // A x4: mats = {rows r, rows r+8} x {k, k+8} of this warp's 16-row block
    uint32_t aoff = ((uint32_t)(w * 16 + (mat & 1) * 8 + lr) * RSH + (uint32_t)(mat >> 1) * 8) * 2;
    // B x4: mat = nt (n-tile), rows n = nt*8 + lr, col = kb (+8 for the b1 load)
    uint32_t boff = ((uint32_t)A_STAGE_H + (uint32_t)(mat * 8 + lr) * RSH) * 2;

    float acc[4][4];
#pragma unroll
    for (int nt = 0; nt < 4; nt++)
#pragma unroll
        for (int q = 0; q < 4; q++) acc[nt][q] = 0.f;

    uint4 ra0, ra1, ra2, ra3, rb0, rb1;
    const int c0 = jz * CPS;

#define LDGC(c) do {                                      \
        const uint4* ap_ = aSrc + (c) * 8 + aseg0;        \
        ra0 = ap_[0]; ra1 = ap_[1]; ra2 = ap_[2]; ra3 = ap_[3]; \
        const uint4* bp_ = bSrc + (c) * 8 + bseg0;        \
        rb0 = bp_[0]; rb1 = bp_[1];                       \
    } while (0)

    LDGC(c0);
    for (int cc = 0; cc < CPS; cc++) {
        int buf = cc & 1;
        {
            __half* dA = &sm2[buf][arow * RSH];
            *(uint4*)(dA + (aseg0 + 0) * 8) = ra0;
            *(uint4*)(dA + (aseg0 + 1) * 8) = ra1;
            *(uint4*)(dA + (aseg0 + 2) * 8) = ra2;
            *(uint4*)(dA + (aseg0 + 3) * 8) = ra3;
            __half* dB = &sm2[buf][A_STAGE_H + brow * RSH];
            *(uint4*)(dB + (bseg0 + 0) * 8) = rb0;
            *(uint4*)(dB + (bseg0 + 1) * 8) = rb1;
        }
        if (cc + 1 < CPS) LDGC(c0 + cc + 1);   // gmem-only: issue before barrier
        __syncthreads();

        uint32_t smb = buf ? smb1 : smb0;

#pragma unroll
        for (int ks = 0; ks < 4; ks++) {
            uint32_t kbB = (uint32_t)ks * 32;   // ks*16 halves in bytes
            uint32_t a0, a1, a2, a3;
            asm volatile("ldmatrix.sync.aligned.m8n8.x4.shared.b16 {%0,%1,%2,%3}, [%4];"
                         : "=r"(a0), "=r"(a1), "=r"(a2), "=r"(a3)
                         : "r"(smb + aoff + kbB));
            uint32_t b0v[4], b1v[4];
            asm volatile("ldmatrix.sync.aligned.m8n8.x4.shared.b16 {%0,%1,%2,%3}, [%4];"
                         : "=r"(b0v[0]), "=r"(b0v[1]), "=r"(b0v[2]), "=r"(b0v[3])
                         : "r"(smb + boff + kbB));
            asm volatile("ldmatrix.sync.aligned.m8n8.x4.shared.b16 {%0,%1,%2,%3}, [%4];"
                         : "=r"(b1v[0]), "=r"(b1v[1]), "=r"(b1v[2]), "=r"(b1v[3])
                         : "r"(smb + boff + kbB + 16));
#pragma unroll
            for (int nt = 0; nt < 4; nt++) {
                asm volatile(
                    "mma.sync.aligned.m16n8k16.row.col.f32.f16.f16.f32 "
                    "{%0,%1,%2,%3}, {%4,%5,%6,%7}, {%8,%9}, {%0,%1,%2,%3};"
                    : "+f"(acc[nt][0]), "+f"(acc[nt][1]),
                      "+f"(acc[nt][2]), "+f"(acc[nt][3])
                    : "r"(a0), "r"(a1), "r"(a2), "r"(a3),
                      "r"(b0v[nt]), "r"(b1v[nt]));
            }
        }
    }

    // epilogue: partial out [jz][b][i][h*32 + d]; undo 2^15
    float* po = g_po + (size_t)jz * (Bq * Nq * Hq * HIDq);
    int r0 = i0 + w * 16 + gro;
#pragma unroll
    for (int nt = 0; nt < 4; nt++) {
        int col = h * HIDq + nt * 8 + 2 * tig;
        float2 v0 = {acc[nt][0] * HT_INV, acc[nt][1] * HT_INV};
        float2 v1 = {acc[nt][2] * HT_INV, acc[nt][3] * HT_INV};
        *(float2*)(po + ((size_t)(b * Nq + r0))     * (Hq * HIDq) + col) = v0;
        *(float2*)(po + ((size_t)(b * Nq + r0 + 8)) * (Hq * HIDq) + col) = v1;
    }
}

// ---------------- k5: reduce partials -> out ----------------
__global__ void k5_reduce(float4* __restrict__ out) {
    int idx = blockIdx.x * 256 + threadIdx.x;   // float4 index
    const float4* po = (const float4*)g_po;
    const int stride = Bq * Nq * Hq * HIDq / 4;
    float4 s = po[idx];
#pragma unroll
    for (int jz = 1; jz < JS; jz++) {
        float4 v = po[(size_t)jz * stride + idx];
        s.x += v.x; s.y += v.y; s.z += v.z; s.w += v.w;
    }
    out[idx] = s;
}

extern "C" void kernel_launch(void* const* d_in, const int* in_sizes, int n_in,
                              void* d_out, int out_size) {
    const float* hin  = (const float*)d_in[0];
    const int*   adj  = (const int*)  d_in[1];
    const float* edge = (const float*)d_in[2];
    const float* W    = (const float*)d_in[3];
    const float* a    = (const float*)d_in[4];
    float* out = (float*)d_out;

    k1_proj<<<Bq * Nq, 128>>>(hin, W, a);
    k2_w<<<dim3(NIC, Nq / 256, Bq), 256>>>(adj, (const float4*)edge, a);
    k3_scale_T<<<dim3(Nq / 256, Bq * Hq), 256>>>();
    k4_mma<<<dim3(Nq / 64, Bq * Hq, JS), 128>>>();
    k5_reduce<<<(Bq * Nq * Hq * HIDq / 4) / 256, 256>>>((float4*)out);
}